// round 1
// baseline (speedup 1.0000x reference)
#include <cuda_runtime.h>
#include <cuda_bf16.h>
#include <stdint.h>

#define RBOX   500000
#define KCLS   10
#define NCAND  (RBOX * KCLS)
#define TTOP   2048
#define SCORE_T 0.05f
#define NMS_T   0.5f
#define CLS_OFF 3001.0f
#define IMG_W   1920.0f
#define IMG_H   1080.0f

// histogram of float bits >> 13, range (0.05, 1.0)
#define HBASE  125542u          // 0x3D4CCCCD >> 13  (bits of 0.05f)
#define HBINS  4506             // up to (bits of ~1.0f) >> 13
#define CAP    4096             // compacted-candidate capacity (>= 2048 + cut-bin spill)
#define ECAP   4096             // NMS edge capacity

// ---------------- device scratch (no allocations allowed) ----------------
__device__ unsigned int       g_hist[HBINS];
__device__ unsigned int       g_cutbin;
__device__ unsigned int       g_cnt;
__device__ unsigned long long g_keys[CAP];
__device__ float              g_nbox[TTOP * 4];   // class-offset boxes for NMS
__device__ float              g_obox[TTOP * 4];   // clipped boxes for output
__device__ float              g_oscore[TTOP];
__device__ unsigned int       g_ecnt;
__device__ unsigned int       g_edges[ECAP];

// ---------------- kernel 1: zero scratch ----------------
__global__ void k_zero() {
    int t = threadIdx.x;
    for (int b = t; b < HBINS; b += blockDim.x) g_hist[b] = 0u;
    if (t == 0) { g_cnt = 0u; g_ecnt = 0u; g_cutbin = 0u; }
}

// ---------------- kernel 2: histogram of fused scores ----------------
__global__ void k_hist(const float* __restrict__ scores,
                       const float* __restrict__ center) {
    unsigned j = blockIdx.x * blockDim.x + threadIdx.x;
    if (j >= NCAND) return;
    unsigned r = j / 10u;
    // scores layout [R,11], candidate j=(r,k) -> offset r*11 + 1 + k = j + r + 1
    float fg = scores[j + r + 1u] * center[r];
    if (fg > SCORE_T) {
        unsigned bin = (__float_as_uint(fg) >> 13) - HBASE;
        if (bin >= HBINS) bin = HBINS - 1;
        atomicAdd(&g_hist[bin], 1u);
    }
}

// ---------------- kernel 3: suffix scan -> cut bin of 2048th value ----------------
__global__ void k_scan() {
    __shared__ unsigned part[1024];
    __shared__ unsigned sincl[1024];
    int t = threadIdx.x;
    const int CH = 5;                       // 1024*5 >= HBINS
    int lo = t * CH;
    int hi = lo + CH; if (hi > HBINS) hi = HBINS; if (lo > HBINS) lo = HBINS;
    unsigned p = 0u;
    for (int b = lo; b < hi; b++) p += g_hist[b];
    part[t] = p; sincl[t] = p;
    __syncthreads();
    // inclusive suffix sum over the 1024 chunk partials
    for (int off = 1; off < 1024; off <<= 1) {
        unsigned v = (t + off < 1024) ? sincl[t + off] : 0u;
        __syncthreads();
        sincl[t] += v;
        __syncthreads();
    }
    unsigned total = sincl[0];
    if (total < TTOP) { if (t == 0) g_cutbin = 0u; return; }
    unsigned above = sincl[t] - part[t];    // count in bins strictly above this chunk
    if (above < TTOP && sincl[t] >= TTOP) { // exactly one thread: crossing in its chunk
        unsigned run = above;
        for (int b = hi - 1; b >= lo; b--) {
            run += g_hist[b];
            if (run >= TTOP) { g_cutbin = (unsigned)b; break; }
        }
    }
}

// ---------------- kernel 4: compact candidates with bin >= cut ----------------
__global__ void k_compact(const float* __restrict__ scores,
                          const float* __restrict__ center) {
    unsigned j = blockIdx.x * blockDim.x + threadIdx.x;
    if (j >= NCAND) return;
    unsigned r = j / 10u;
    float fg = scores[j + r + 1u] * center[r];
    if (fg > SCORE_T) {
        unsigned bits = __float_as_uint(fg);
        unsigned bin = (bits >> 13) - HBASE;
        if (bin >= HBINS) bin = HBINS - 1;
        if (bin >= g_cutbin) {
            unsigned pos = atomicAdd(&g_cnt, 1u);
            if (pos < CAP) {
                // key: score desc, then index asc (matches jax.lax.top_k tie-break)
                g_keys[pos] = ((unsigned long long)bits << 32) |
                              (unsigned long long)(0xFFFFFFFFu - j);
            }
        }
    }
}

// ---------------- kernel 5: bitonic sort top candidates + gather boxes ----------------
__global__ void k_sortgather(const float* __restrict__ boxes) {
    __shared__ unsigned long long sk[CAP];  // 32 KB
    int t = threadIdx.x;
    unsigned n = g_cnt; if (n > CAP) n = CAP;
    for (int i = t; i < CAP; i += 1024) sk[i] = (i < (int)n) ? g_keys[i] : 0ull;
    __syncthreads();
    // bitonic sort, DESCENDING
    for (unsigned k = 2; k <= CAP; k <<= 1) {
        for (unsigned jj = k >> 1; jj > 0; jj >>= 1) {
            for (unsigned i = t; i < CAP; i += 1024) {
                unsigned ixj = i ^ jj;
                if (ixj > i) {
                    bool up = ((i & k) != 0);   // flipped -> descending overall
                    unsigned long long a = sk[i], b = sk[ixj];
                    bool sw = up ? (a > b) : (a < b);
                    if (sw) { sk[i] = b; sk[ixj] = a; }
                }
            }
            __syncthreads();
        }
    }
    for (int i = t; i < TTOP; i += 1024) {
        unsigned long long key = sk[i];
        float s = __uint_as_float((unsigned)(key >> 32));
        float b0 = 0.f, b1 = 0.f, b2 = 0.f, b3 = 0.f;
        float n0 = 0.f, n1 = 0.f, n2 = 0.f, n3 = 0.f, sc = 0.f;
        if (s > SCORE_T) {
            unsigned j = 0xFFFFFFFFu - (unsigned)(key & 0xFFFFFFFFull);
            unsigned r = j / 10u;
            unsigned cls = j - r * 10u;
            float x1 = boxes[r * 4 + 0], y1 = boxes[r * 4 + 1];
            float x2 = boxes[r * 4 + 2], y2 = boxes[r * 4 + 3];
            b0 = fminf(fmaxf(x1, 0.f), IMG_W);
            b1 = fminf(fmaxf(y1, 0.f), IMG_H);
            b2 = fminf(fmaxf(x2, 0.f), IMG_W);
            b3 = fminf(fmaxf(y2, 0.f), IMG_H);
            float off = (float)cls * CLS_OFF;
            n0 = b0 + off; n1 = b1 + off; n2 = b2 + off; n3 = b3 + off;
            sc = s;
        }
        g_obox[i * 4 + 0] = b0; g_obox[i * 4 + 1] = b1;
        g_obox[i * 4 + 2] = b2; g_obox[i * 4 + 3] = b3;
        g_nbox[i * 4 + 0] = n0; g_nbox[i * 4 + 1] = n1;
        g_nbox[i * 4 + 2] = n2; g_nbox[i * 4 + 3] = n3;
        g_oscore[i] = sc;
    }
}

// ---------------- kernel 6: pairwise IoU -> sparse suppression edges ----------------
__global__ void k_edges() {
    int bi = blockIdx.y, bj = blockIdx.x;
    if (bj < bi) return;                    // need j > i; whole tile below diagonal skipped
    __shared__ float jb[64 * 4];
    int t = threadIdx.x;                    // 64 threads
    int jbase = bj * 64;
    for (int q = t; q < 256; q += 64) jb[q] = g_nbox[jbase * 4 + q];
    __syncthreads();
    int i = bi * 64 + t;
    float ax1 = g_nbox[i * 4 + 0], ay1 = g_nbox[i * 4 + 1];
    float ax2 = g_nbox[i * 4 + 2], ay2 = g_nbox[i * 4 + 3];
    float aarea = fmaxf(ax2 - ax1, 0.f) * fmaxf(ay2 - ay1, 0.f);
    for (int q = 0; q < 64; q++) {
        int j = jbase + q;
        if (j <= i) continue;
        float bx1 = jb[q * 4 + 0], by1 = jb[q * 4 + 1];
        float bx2 = jb[q * 4 + 2], by2 = jb[q * 4 + 3];
        float barea = fmaxf(bx2 - bx1, 0.f) * fmaxf(by2 - by1, 0.f);
        float w = fmaxf(fminf(ax2, bx2) - fmaxf(ax1, bx1), 0.f);
        float h = fmaxf(fminf(ay2, by2) - fmaxf(ay1, by1), 0.f);
        float inter = w * h;
        float iou = inter / (aarea + barea - inter + 1e-9f);  // exact reference formula
        if (iou > NMS_T) {
            unsigned pos = atomicAdd(&g_ecnt, 1u);
            if (pos < ECAP) g_edges[pos] = ((unsigned)i << 16) | (unsigned)j;
        }
    }
}

// ---------------- kernel 7: sort edges, greedy suppression replay, write output ----------------
__global__ void k_final(float* __restrict__ out) {
    __shared__ unsigned se[ECAP];           // 16 KB
    __shared__ unsigned char keep[TTOP];    // 2 KB
    int t = threadIdx.x;
    unsigned E = g_ecnt; if (E > ECAP) E = ECAP;
    for (int i = t; i < ECAP; i += 1024) se[i] = (i < (int)E) ? g_edges[i] : 0xFFFFFFFFu;
    for (int i = t; i < TTOP; i += 1024) keep[i] = (g_oscore[i] > SCORE_T) ? 1 : 0;
    __syncthreads();

    if (E > 1) {
        // next power of two >= E, min 2
        unsigned P = 2;
        while (P < E) P <<= 1;
        // bitonic sort ASCENDING on packed (i<<16|j)
        for (unsigned k = 2; k <= P; k <<= 1) {
            for (unsigned jj = k >> 1; jj > 0; jj >>= 1) {
                for (unsigned i = t; i < P; i += 1024) {
                    unsigned ixj = i ^ jj;
                    if (ixj > i) {
                        bool up = ((i & k) == 0);
                        unsigned a = se[i], b = se[ixj];
                        bool sw = up ? (a > b) : (a < b);
                        if (sw) { se[i] = b; se[ixj] = a; }
                    }
                }
                __syncthreads();
            }
        }
    }
    // sequential greedy replay: edges grouped by ascending i -> exact equivalence
    // to the reference fori_loop (suppressor i's own keep state is final when reached)
    if (t == 0) {
        for (unsigned e = 0; e < E; e++) {
            unsigned v = se[e];
            unsigned i = v >> 16, j = v & 0xFFFFu;
            if (keep[i]) keep[j] = 0;
        }
    }
    __syncthreads();
    for (int i = t; i < TTOP; i += 1024) {
        bool kp = keep[i] != 0;
        out[i * 5 + 0] = kp ? g_obox[i * 4 + 0] : 0.f;
        out[i * 5 + 1] = kp ? g_obox[i * 4 + 1] : 0.f;
        out[i * 5 + 2] = kp ? g_obox[i * 4 + 2] : 0.f;
        out[i * 5 + 3] = kp ? g_obox[i * 4 + 3] : 0.f;
        out[i * 5 + 4] = kp ? g_oscore[i] : 0.f;
    }
}

// ---------------- launch ----------------
extern "C" void kernel_launch(void* const* d_in, const int* in_sizes, int n_in,
                              void* d_out, int out_size) {
    const float* boxes  = nullptr;
    const float* scores = nullptr;
    const float* center = nullptr;
    for (int i = 0; i < n_in; i++) {
        if (in_sizes[i] == RBOX * 4)      boxes  = (const float*)d_in[i];
        else if (in_sizes[i] == RBOX * 11) scores = (const float*)d_in[i];
        else if (in_sizes[i] == RBOX)      center = (const float*)d_in[i];
    }
    if (!boxes)  boxes  = (const float*)d_in[0];
    if (!scores) scores = (const float*)d_in[1];
    if (!center) center = (const float*)d_in[2];
    float* out = (float*)d_out;

    const int TPB = 256;
    const int GBIG = (NCAND + TPB - 1) / TPB;

    k_zero<<<1, 1024>>>();
    k_hist<<<GBIG, TPB>>>(scores, center);
    k_scan<<<1, 1024>>>();
    k_compact<<<GBIG, TPB>>>(scores, center);
    k_sortgather<<<1, 1024>>>(boxes);
    k_edges<<<dim3(32, 32), 64>>>();
    k_final<<<1, 1024>>>(out);
}

// round 2
// speedup vs baseline: 1.7839x; 1.7839x over previous
#include <cuda_runtime.h>
#include <cuda_bf16.h>
#include <stdint.h>

#define RBOX   500000
#define KCLS   10
#define NCAND  (RBOX * KCLS)
#define NSCAL  (RBOX * 11)          // 5,500,000 floats in scores
#define NV4    (NSCAL / 4)          // 1,375,000 float4s (exact)
#define TTOP   2048
#define SCORE_T 0.05f
#define NMS_T   0.5f
#define CLS_OFF 3001.0f
#define IMG_W   1920.0f
#define IMG_H   1080.0f

// histogram of float bits >> 13, range (0.05, 1.0)
#define HBASE  125542u              // 0x3D4CCCCD >> 13  (bits of 0.05f)
#define HBINS  4506
#define CAP    4096
#define ECAP   4096

// ---------------- device scratch ----------------
__device__ unsigned int       g_hist[HBINS];
__device__ unsigned int       g_cutbin;
__device__ unsigned int       g_cnt;
__device__ unsigned long long g_keys[CAP];
__device__ float              g_nbox[TTOP * 4];
__device__ float              g_obox[TTOP * 4];
__device__ float              g_oscore[TTOP];
__device__ unsigned int       g_ecnt;
__device__ unsigned int       g_edges[ECAP];

// ---------------- kernel 1: zero scratch ----------------
__global__ void k_zero() {
    int t = threadIdx.x;
    for (int b = t; b < HBINS; b += blockDim.x) g_hist[b] = 0u;
    if (t == 0) { g_cnt = 0u; g_ecnt = 0u; g_cutbin = 0u; }
}

// ---------------- kernel 2: histogram (smem-privatized, float4) ----------------
__global__ void __launch_bounds__(1024, 2) k_hist(const float* __restrict__ scores,
                                                  const float* __restrict__ center) {
    __shared__ unsigned sh[HBINS];      // 18 KB
    int t = threadIdx.x;
    for (int b = t; b < HBINS; b += 1024) sh[b] = 0u;
    __syncthreads();

    const float4* s4 = (const float4*)scores;
    unsigned stride = gridDim.x * 1024u;
    for (unsigned q = blockIdx.x * 1024u + t; q < NV4; q += stride) {
        float4 v = __ldg(&s4[q]);
        unsigned gi = q * 4u;
        #pragma unroll
        for (int e = 0; e < 4; e++) {
            float val = (e == 0) ? v.x : (e == 1) ? v.y : (e == 2) ? v.z : v.w;
            unsigned g = gi + e;
            unsigned r = g / 11u;
            unsigned c = g - r * 11u;
            if (c != 0u) {
                float fg = val * __ldg(&center[r]);
                if (fg > SCORE_T) {
                    unsigned bin = (__float_as_uint(fg) >> 13) - HBASE;
                    if (bin >= HBINS) bin = HBINS - 1;
                    atomicAdd(&sh[bin], 1u);
                }
            }
        }
    }
    __syncthreads();
    for (int b = t; b < HBINS; b += 1024) {
        unsigned v = sh[b];
        if (v) atomicAdd(&g_hist[b], v);
    }
}

// ---------------- kernel 3: suffix scan -> cut bin of 2048th value ----------------
__global__ void k_scan() {
    __shared__ unsigned part[1024];
    __shared__ unsigned sincl[1024];
    int t = threadIdx.x;
    const int CH = 5;
    int lo = t * CH;
    int hi = lo + CH; if (hi > HBINS) hi = HBINS; if (lo > HBINS) lo = HBINS;
    unsigned p = 0u;
    for (int b = lo; b < hi; b++) p += g_hist[b];
    part[t] = p; sincl[t] = p;
    __syncthreads();
    for (int off = 1; off < 1024; off <<= 1) {
        unsigned v = (t + off < 1024) ? sincl[t + off] : 0u;
        __syncthreads();
        sincl[t] += v;
        __syncthreads();
    }
    unsigned total = sincl[0];
    if (total < TTOP) { if (t == 0) g_cutbin = 0u; return; }
    unsigned above = sincl[t] - part[t];
    if (above < TTOP && sincl[t] >= TTOP) {
        unsigned run = above;
        for (int b = hi - 1; b >= lo; b--) {
            run += g_hist[b];
            if (run >= TTOP) { g_cutbin = (unsigned)b; break; }
        }
    }
}

// ---------------- kernel 4: compact candidates (float4) ----------------
__global__ void k_compact(const float* __restrict__ scores,
                          const float* __restrict__ center) {
    unsigned q = blockIdx.x * blockDim.x + threadIdx.x;
    if (q >= NV4) return;
    unsigned cut = g_cutbin;
    float4 v = __ldg(&((const float4*)scores)[q]);
    unsigned gi = q * 4u;
    #pragma unroll
    for (int e = 0; e < 4; e++) {
        float val = (e == 0) ? v.x : (e == 1) ? v.y : (e == 2) ? v.z : v.w;
        unsigned g = gi + e;
        unsigned r = g / 11u;
        unsigned c = g - r * 11u;
        if (c != 0u) {
            float fg = val * __ldg(&center[r]);
            if (fg > SCORE_T) {
                unsigned bits = __float_as_uint(fg);
                unsigned bin = (bits >> 13) - HBASE;
                if (bin >= HBINS) bin = HBINS - 1;
                if (bin >= cut) {
                    unsigned j = r * 10u + (c - 1u);     // candidate index in [R*K)
                    unsigned pos = atomicAdd(&g_cnt, 1u);
                    if (pos < CAP) {
                        g_keys[pos] = ((unsigned long long)bits << 32) |
                                      (unsigned long long)(0xFFFFFFFFu - j);
                    }
                }
            }
        }
    }
}

// ---------------- kernel 5: bitonic sort top candidates + gather boxes ----------------
__global__ void k_sortgather(const float* __restrict__ boxes) {
    __shared__ unsigned long long sk[CAP];  // 32 KB
    int t = threadIdx.x;
    unsigned n = g_cnt; if (n > CAP) n = CAP;
    for (int i = t; i < CAP; i += 1024) sk[i] = (i < (int)n) ? g_keys[i] : 0ull;
    __syncthreads();
    for (unsigned k = 2; k <= CAP; k <<= 1) {
        for (unsigned jj = k >> 1; jj > 0; jj >>= 1) {
            for (unsigned i = t; i < CAP; i += 1024) {
                unsigned ixj = i ^ jj;
                if (ixj > i) {
                    bool up = ((i & k) != 0);   // descending overall
                    unsigned long long a = sk[i], b = sk[ixj];
                    bool sw = up ? (a > b) : (a < b);
                    if (sw) { sk[i] = b; sk[ixj] = a; }
                }
            }
            __syncthreads();
        }
    }
    for (int i = t; i < TTOP; i += 1024) {
        unsigned long long key = sk[i];
        float s = __uint_as_float((unsigned)(key >> 32));
        float b0 = 0.f, b1 = 0.f, b2 = 0.f, b3 = 0.f;
        float n0 = 0.f, n1 = 0.f, n2 = 0.f, n3 = 0.f, sc = 0.f;
        if (s > SCORE_T) {
            unsigned j = 0xFFFFFFFFu - (unsigned)(key & 0xFFFFFFFFull);
            unsigned r = j / 10u;
            unsigned cls = j - r * 10u;
            float x1 = boxes[r * 4 + 0], y1 = boxes[r * 4 + 1];
            float x2 = boxes[r * 4 + 2], y2 = boxes[r * 4 + 3];
            b0 = fminf(fmaxf(x1, 0.f), IMG_W);
            b1 = fminf(fmaxf(y1, 0.f), IMG_H);
            b2 = fminf(fmaxf(x2, 0.f), IMG_W);
            b3 = fminf(fmaxf(y2, 0.f), IMG_H);
            float off = (float)cls * CLS_OFF;
            n0 = b0 + off; n1 = b1 + off; n2 = b2 + off; n3 = b3 + off;
            sc = s;
        }
        g_obox[i * 4 + 0] = b0; g_obox[i * 4 + 1] = b1;
        g_obox[i * 4 + 2] = b2; g_obox[i * 4 + 3] = b3;
        g_nbox[i * 4 + 0] = n0; g_nbox[i * 4 + 1] = n1;
        g_nbox[i * 4 + 2] = n2; g_nbox[i * 4 + 3] = n3;
        g_oscore[i] = sc;
    }
}

// ---------------- kernel 6: pairwise IoU -> sparse suppression edges ----------------
__global__ void k_edges() {
    int bi = blockIdx.y, bj = blockIdx.x;
    if (bj < bi) return;
    __shared__ float jb[64 * 4];
    int t = threadIdx.x;                    // 64 threads
    int jbase = bj * 64;
    for (int q = t; q < 256; q += 64) jb[q] = g_nbox[jbase * 4 + q];
    __syncthreads();
    int i = bi * 64 + t;
    float ax1 = g_nbox[i * 4 + 0], ay1 = g_nbox[i * 4 + 1];
    float ax2 = g_nbox[i * 4 + 2], ay2 = g_nbox[i * 4 + 3];
    float aarea = fmaxf(ax2 - ax1, 0.f) * fmaxf(ay2 - ay1, 0.f);
    for (int q = 0; q < 64; q++) {
        int j = jbase + q;
        if (j <= i) continue;
        float bx1 = jb[q * 4 + 0], by1 = jb[q * 4 + 1];
        float bx2 = jb[q * 4 + 2], by2 = jb[q * 4 + 3];
        float barea = fmaxf(bx2 - bx1, 0.f) * fmaxf(by2 - by1, 0.f);
        float w = fmaxf(fminf(ax2, bx2) - fmaxf(ax1, bx1), 0.f);
        float h = fmaxf(fminf(ay2, by2) - fmaxf(ay1, by1), 0.f);
        float inter = w * h;
        float iou = inter / (aarea + barea - inter + 1e-9f);
        if (iou > NMS_T) {
            unsigned pos = atomicAdd(&g_ecnt, 1u);
            if (pos < ECAP) g_edges[pos] = ((unsigned)i << 16) | (unsigned)j;
        }
    }
}

// ---------------- kernel 7: sort edges, greedy replay, write output ----------------
__global__ void k_final(float* __restrict__ out) {
    __shared__ unsigned se[ECAP];
    __shared__ unsigned char keep[TTOP];
    int t = threadIdx.x;
    unsigned E = g_ecnt; if (E > ECAP) E = ECAP;
    for (int i = t; i < ECAP; i += 1024) se[i] = (i < (int)E) ? g_edges[i] : 0xFFFFFFFFu;
    for (int i = t; i < TTOP; i += 1024) keep[i] = (g_oscore[i] > SCORE_T) ? 1 : 0;
    __syncthreads();

    if (E > 1) {
        unsigned P = 2;
        while (P < E) P <<= 1;
        for (unsigned k = 2; k <= P; k <<= 1) {
            for (unsigned jj = k >> 1; jj > 0; jj >>= 1) {
                for (unsigned i = t; i < P; i += 1024) {
                    unsigned ixj = i ^ jj;
                    if (ixj > i) {
                        bool up = ((i & k) == 0);
                        unsigned a = se[i], b = se[ixj];
                        bool sw = up ? (a > b) : (a < b);
                        if (sw) { se[i] = b; se[ixj] = a; }
                    }
                }
                __syncthreads();
            }
        }
    }
    if (t == 0) {
        for (unsigned e = 0; e < E; e++) {
            unsigned v = se[e];
            unsigned i = v >> 16, j = v & 0xFFFFu;
            if (keep[i]) keep[j] = 0;
        }
    }
    __syncthreads();
    for (int i = t; i < TTOP; i += 1024) {
        bool kp = keep[i] != 0;
        out[i * 5 + 0] = kp ? g_obox[i * 4 + 0] : 0.f;
        out[i * 5 + 1] = kp ? g_obox[i * 4 + 1] : 0.f;
        out[i * 5 + 2] = kp ? g_obox[i * 4 + 2] : 0.f;
        out[i * 5 + 3] = kp ? g_obox[i * 4 + 3] : 0.f;
        out[i * 5 + 4] = kp ? g_oscore[i] : 0.f;
    }
}

// ---------------- launch ----------------
extern "C" void kernel_launch(void* const* d_in, const int* in_sizes, int n_in,
                              void* d_out, int out_size) {
    const float* boxes  = nullptr;
    const float* scores = nullptr;
    const float* center = nullptr;
    for (int i = 0; i < n_in; i++) {
        if (in_sizes[i] == RBOX * 4)       boxes  = (const float*)d_in[i];
        else if (in_sizes[i] == RBOX * 11) scores = (const float*)d_in[i];
        else if (in_sizes[i] == RBOX)      center = (const float*)d_in[i];
    }
    if (!boxes)  boxes  = (const float*)d_in[0];
    if (!scores) scores = (const float*)d_in[1];
    if (!center) center = (const float*)d_in[2];
    float* out = (float*)d_out;

    k_zero<<<1, 1024>>>();
    k_hist<<<296, 1024>>>(scores, center);
    k_scan<<<1, 1024>>>();
    k_compact<<<(NV4 + 255) / 256, 256>>>(scores, center);
    k_sortgather<<<1, 1024>>>(boxes);
    k_edges<<<dim3(32, 32), 64>>>();
    k_final<<<1, 1024>>>(out);
}